// round 5
// baseline (speedup 1.0000x reference)
#include <cuda_runtime.h>
#include <cuda_bf16.h>

// Comparator4Bit: A,B are (N,4) float32 with values in {0,1}.
// col0 = MSB ... col3 = LSB of a 4-bit number.
// out[0:N] = (valA > valB) ? 1.0f : 0.0f;  out[N:2N] = (valA == valB) ? 1.0f : 0.0f
//
// HBM-bound streaming: 128 MiB read + 32 MiB write (~5.9-6.0 TB/s = ceiling
// for mixed traffic on this part). Best structure found (R3): flat launch,
// 2 rows/thread, 4x LDG.128 front-batched, float2 stores, 8 CTAs/SM.
// Compare via 64-bit lexicographic unsigned compare: words are 0x0/0x3F800000,
// so (col0<<32|col1, col2<<32|col3) ordering == 4-bit numeric ordering.

static __device__ __forceinline__ void row_keys(const uint4 v,
                                                unsigned long long& hi,
                                                unsigned long long& lo) {
    hi = ((unsigned long long)v.x << 32) | v.y;   // col0 (MSB), col1
    lo = ((unsigned long long)v.z << 32) | v.w;   // col2, col3 (LSB)
}

__global__ void __launch_bounds__(256, 8)
comparator4bit_kernel(const uint4* __restrict__ A4,
                      const uint4* __restrict__ B4,
                      float2* __restrict__ out_gt2,
                      float2* __restrict__ out_eq2,
                      int n_units)   // n_rows / 2 work units
{
    int t = blockIdx.x * blockDim.x + threadIdx.x;
    if (t >= n_units) return;
    int base = t * 2;

    // Front-batch all 4 loads for max MLP.
    uint4 a0 = A4[base + 0];
    uint4 a1 = A4[base + 1];
    uint4 b0 = B4[base + 0];
    uint4 b1 = B4[base + 1];

    unsigned long long ah0, al0, bh0, bl0, ah1, al1, bh1, bl1;
    row_keys(a0, ah0, al0);  row_keys(b0, bh0, bl0);
    row_keys(a1, ah1, al1);  row_keys(b1, bh1, bl1);

    bool he0 = (ah0 == bh0);
    bool he1 = (ah1 == bh1);

    float2 gt, eq;
    gt.x = ((ah0 > bh0) || (he0 && al0 > bl0)) ? 1.0f : 0.0f;
    eq.x = (he0 && al0 == bl0) ? 1.0f : 0.0f;
    gt.y = ((ah1 > bh1) || (he1 && al1 > bl1)) ? 1.0f : 0.0f;
    eq.y = (he1 && al1 == bl1) ? 1.0f : 0.0f;

    out_gt2[t] = gt;
    out_eq2[t] = eq;
}

extern "C" void kernel_launch(void* const* d_in, const int* in_sizes, int n_in,
                              void* d_out, int out_size) {
    const float* A = (const float*)d_in[0];
    const float* B = (const float*)d_in[1];
    float* out = (float*)d_out;

    int n_rows = in_sizes[0] / 4;   // (N,4) float32 -> N rows
    int n_units = n_rows / 2;       // 2 rows per thread

    float* out_gt = out;            // [0:N)
    float* out_eq = out + n_rows;   // [N:2N)

    const int threads = 256;
    int blocks = (n_units + threads - 1) / threads;

    comparator4bit_kernel<<<blocks, threads>>>(
        (const uint4*)A, (const uint4*)B,
        (float2*)out_gt, (float2*)out_eq, n_units);
}

// round 6
// speedup vs baseline: 1.0088x; 1.0088x over previous
#include <cuda_runtime.h>
#include <cuda_bf16.h>

// Comparator4Bit: A,B are (N,4) float32 with values in {0,1}.
// col0 = MSB ... col3 = LSB of a 4-bit number.
// out[0:N] = (valA > valB) ? 1.0f : 0.0f;  out[N:2N] = (valA == valB) ? 1.0f : 0.0f
//
// HBM-bound streaming (128 MiB read + 32 MiB write). Finest-grain shape:
// 1 row/thread, 2x LDG.128 + 2x STG.32, ~16 regs, 8 CTAs/SM, 16384 blocks —
// maximizes achieved occupancy / evenness of DRAM demand.
// Compare via 64-bit lexicographic unsigned compare: words are 0x0/0x3F800000,
// so (col0<<32|col1, col2<<32|col3) ordering == 4-bit numeric ordering.

__global__ void __launch_bounds__(256, 8)
comparator4bit_kernel(const uint4* __restrict__ A4,
                      const uint4* __restrict__ B4,
                      float* __restrict__ out_gt,
                      float* __restrict__ out_eq,
                      int n_rows)
{
    int t = blockIdx.x * blockDim.x + threadIdx.x;
    if (t >= n_rows) return;

    uint4 a = A4[t];
    uint4 b = B4[t];

    unsigned long long ah = ((unsigned long long)a.x << 32) | a.y;  // col0,col1
    unsigned long long al = ((unsigned long long)a.z << 32) | a.w;  // col2,col3
    unsigned long long bh = ((unsigned long long)b.x << 32) | b.y;
    unsigned long long bl = ((unsigned long long)b.z << 32) | b.w;

    bool he = (ah == bh);
    out_gt[t] = ((ah > bh) || (he && al > bl)) ? 1.0f : 0.0f;
    out_eq[t] = (he && al == bl) ? 1.0f : 0.0f;
}

extern "C" void kernel_launch(void* const* d_in, const int* in_sizes, int n_in,
                              void* d_out, int out_size) {
    const float* A = (const float*)d_in[0];
    const float* B = (const float*)d_in[1];
    float* out = (float*)d_out;

    int n_rows = in_sizes[0] / 4;   // (N,4) float32 -> N rows

    float* out_gt = out;            // [0:N)
    float* out_eq = out + n_rows;   // [N:2N)

    const int threads = 256;
    int blocks = (n_rows + threads - 1) / threads;

    comparator4bit_kernel<<<blocks, threads>>>(
        (const uint4*)A, (const uint4*)B, out_gt, out_eq, n_rows);
}